// round 2
// baseline (speedup 1.0000x reference)
#include <cuda_runtime.h>
#include <stdint.h>

#define NSTEP 1000
#define NELEM 45056      // 16*1*64*44
#define HW    2816       // 64*44
#define QELEM 11264      // NELEM/4 (quarter-step granule)
#define NB_SOLVE 176     // NELEM/256
#define NB_NOISE 500
#define NPASS 8          // 4000 quarter-tasks / 500 blocks

__device__ float g_noise[(size_t)NSTEP * NELEM];
__device__ int   g_flag[NSTEP];

// =================== compile-time schedule + keys ===================
struct SchedData {
  float P[NSTEP], Q[NSTEP], C1[NSTEP], TCO[NSTEP];
  unsigned K0[NSTEP], K1[NSTEP];
};

constexpr double csqrt(double x) {
  double r = (x > 1.0) ? x : 1.0;
  for (int i = 0; i < 48; i++) r = 0.5 * (r + x / r);
  return r;
}
constexpr unsigned crotl(unsigned v, int r) { return (v << r) | (v >> (32 - r)); }
constexpr void ctf_round(unsigned& x0, unsigned& x1, int r) {
  x0 += x1; x1 = crotl(x1, r); x1 ^= x0;
}
constexpr void cthreefry(unsigned ks0, unsigned ks1, unsigned x0, unsigned x1,
                         unsigned& o0, unsigned& o1) {
  const unsigned ks2 = ks0 ^ ks1 ^ 0x1BD11BDAu;
  x0 += ks0; x1 += ks1;
  ctf_round(x0,x1,13); ctf_round(x0,x1,15); ctf_round(x0,x1,26); ctf_round(x0,x1,6);
  x0 += ks1; x1 += ks2 + 1u;
  ctf_round(x0,x1,17); ctf_round(x0,x1,29); ctf_round(x0,x1,16); ctf_round(x0,x1,24);
  x0 += ks2; x1 += ks0 + 2u;
  ctf_round(x0,x1,13); ctf_round(x0,x1,15); ctf_round(x0,x1,26); ctf_round(x0,x1,6);
  x0 += ks0; x1 += ks1 + 3u;
  ctf_round(x0,x1,17); ctf_round(x0,x1,29); ctf_round(x0,x1,16); ctf_round(x0,x1,24);
  x0 += ks1; x1 += ks2 + 4u;
  ctf_round(x0,x1,13); ctf_round(x0,x1,15); ctf_round(x0,x1,26); ctf_round(x0,x1,6);
  o0 = x0 + ks2;
  o1 = x1 + ks0 + 5u;
}

constexpr SchedData make_sched() {
  SchedData s{};
  double alph[NSTEP + 1] = {};
  alph[0] = 1.0;
  {
    double prod = 1.0;
    const double bstep = (0.02 - 1e-4) / 999.0;
    for (int i = 0; i < NSTEP; i++) {
      double beta = (i == 999) ? 0.02 : (1e-4 + (double)i * bstep);
      prod *= (1.0 - beta);
      alph[i + 1] = prod;
    }
  }
  for (int k = 0; k < NSTEP; k++) {
    const int idx = 999 - k;
    const float at  = (float)alph[idx + 1];
    const float atn = (float)alph[idx];            // k==999 -> 1.0
    const float a1  = 1.0f - at / atn;
    const float c1  = 0.1f * (float)csqrt((double)(a1 * (1.0f - atn) / (1.0f - at)));
    float t2 = 1.0f - atn - c1 * c1; if (t2 < 0.0f) t2 = 0.0f;
    const float c2  = (float)csqrt((double)t2);
    const double s1 = csqrt(1.0 - (double)at);
    const double Qd = (double)c2 / s1;                               // coeff of sil_T
    const double Pd = (double)(float)csqrt((double)atn)
                    - Qd * (double)(float)csqrt((double)at);         // coeff of sil_0
    s.P[k] = (float)Pd; s.Q[k] = (float)Qd; s.C1[k] = c1;
    s.TCO[k] = (float)idx / 1000.0f;
    unsigned k0 = 0, k1 = 0;
    cthreefry(0u, 42u, 0u, (unsigned)idx, k0, k1);   // fold_in(key(42), idx)
    s.K0[k] = k0; s.K1[k] = k1;
  }
  return s;
}

constexpr SchedData H_SCHED = make_sched();
__constant__ SchedData C = H_SCHED;

// =================== device threefry + normal ===================
__device__ __forceinline__ void tf_round(uint32_t& x0, uint32_t& x1, int r) {
  x0 += x1;
  x1 = __funnelshift_l(x1, x1, r);
  x1 ^= x0;
}
__device__ __forceinline__ void threefry2x32(uint32_t ks0, uint32_t ks1,
                                             uint32_t x0, uint32_t x1,
                                             uint32_t& o0, uint32_t& o1) {
  const uint32_t ks2 = ks0 ^ ks1 ^ 0x1BD11BDAu;
  x0 += ks0; x1 += ks1;
  tf_round(x0,x1,13); tf_round(x0,x1,15); tf_round(x0,x1,26); tf_round(x0,x1,6);
  x0 += ks1; x1 += ks2 + 1u;
  tf_round(x0,x1,17); tf_round(x0,x1,29); tf_round(x0,x1,16); tf_round(x0,x1,24);
  x0 += ks2; x1 += ks0 + 2u;
  tf_round(x0,x1,13); tf_round(x0,x1,15); tf_round(x0,x1,26); tf_round(x0,x1,6);
  x0 += ks0; x1 += ks1 + 3u;
  tf_round(x0,x1,17); tf_round(x0,x1,29); tf_round(x0,x1,16); tf_round(x0,x1,24);
  x0 += ks1; x1 += ks2 + 4u;
  tf_round(x0,x1,13); tf_round(x0,x1,15); tf_round(x0,x1,26); tf_round(x0,x1,6);
  o0 = x0 + ks2;
  o1 = x1 + ks0 + 5u;
}

__device__ __forceinline__ float bits_to_normal(uint32_t bits) {
  float f = __uint_as_float((bits >> 9) | 0x3f800000u) - 1.0f;  // [0,1)
  float u = fmaf(f, 2.0f, -0.99999994f);                        // (hi-lo) == 2.0f
  float w = -__logf(fmaf(-u, u, 1.0f));
  float p;
  if (w < 5.0f) {  // XLA ErfInv32 (Giles)
    w -= 2.5f;
    p =             2.81022636e-08f;
    p = fmaf(p, w,  3.43273939e-07f);
    p = fmaf(p, w, -3.5233877e-06f);
    p = fmaf(p, w, -4.39150654e-06f);
    p = fmaf(p, w,  0.00021858087f);
    p = fmaf(p, w, -0.00125372503f);
    p = fmaf(p, w, -0.00417768164f);
    p = fmaf(p, w,  0.246640727f);
    p = fmaf(p, w,  1.50140941f);
  } else {
    w = sqrtf(w) - 3.0f;
    p =            -0.000200214257f;
    p = fmaf(p, w,  0.000100950558f);
    p = fmaf(p, w,  0.00134934322f);
    p = fmaf(p, w, -0.00367342844f);
    p = fmaf(p, w,  0.00573950773f);
    p = fmaf(p, w, -0.0076224613f);
    p = fmaf(p, w,  0.00943887047f);
    p = fmaf(p, w,  1.00167406f);
    p = fmaf(p, w,  2.83297682f);
  }
  return 1.41421356f * (p * u);
}

// =================== fused producer/consumer kernel ===================
__global__ void __launch_bounds__(256) fused_kernel(
    const float* __restrict__ skes, const float* __restrict__ silT_g,
    const float* __restrict__ w_skes, const float* __restrict__ w_sil_p,
    const float* __restrict__ t_scale_p, float* __restrict__ preds)
{
  const int bid = blockIdx.x;
  const int tid = threadIdx.x;

  if (bid >= NB_SOLVE) {
    // ---------- noise producer: 8 passes of quarter-step tasks ----------
    const int nb = bid - NB_SOLVE;             // 0..499
    for (int pass = 0; pass < NPASS; pass++) {
      const int task = pass * NB_NOISE + nb;   // 0..3999
      const int s = task >> 2;                 // step
      const int q = task & 3;                  // quarter
      const uint32_t ks0 = C.K0[s], ks1 = C.K1[s];
      float* out = g_noise + (size_t)s * NELEM + q * QELEM;
      const uint32_t ibase = (uint32_t)(q * QELEM + tid);
#pragma unroll 2
      for (int j = 0; j < 44; j++) {
        uint32_t o0, o1;
        threefry2x32(ks0, ks1, 0u, ibase + (uint32_t)(j * 256), o0, o1);
        out[tid + j * 256] = bits_to_normal(o0 ^ o1);
      }
      __syncthreads();                         // all quarter writes issued
      if (tid == 0) {
        __threadfence();                       // release
        atomicAdd(&g_flag[s], 1);              // step ready when == 4
      }
    }
    return;
  }

  // ---------- sequential DDIM solve ----------
  const int i  = bid * 256 + tid;              // < 45056 exactly
  const int ns = i / HW;
  const int r  = i - ns * HW;
  const int n  = ns >> 3, sf = ns & 7;
  const float* bp = skes + (size_t)(n * 24 + sf) * HW + r;  // c stride = 8*HW
  const float cond = bp[0] * w_skes[0] + bp[8 * HW] * w_skes[1] + bp[16 * HW] * w_skes[2];
  const float silT = silT_g[i];
  const float wsil = *w_sil_p;
  const float tsc  = *t_scale_p;

  float sil = silT;
  const float* ng = g_noise + i;
  float* op = preds + i;

  for (int kb = 0; kb < NSTEP; kb += 8) {
    if (tid == 0) {
#pragma unroll 1
      for (int j = 0; j < 8; j++) {
        while (*(volatile int*)&g_flag[kb + j] < 4) __nanosleep(64);
      }
      __threadfence();                         // acquire
    }
    __syncthreads();
    float nz[8];
#pragma unroll
    for (int u = 0; u < 8; u++) nz[u] = ng[(size_t)(kb + u) * NELEM];
#pragma unroll
    for (int u = 0; u < 8; u++) {
      const int k = kb + u;
      const float z  = fmaf(wsil, sil, fmaf(tsc, C.TCO[k], cond));
      const float s0 = tanhf(z);
      op[(size_t)k * NELEM] = s0;
      sil = fmaf(C.P[k], s0, fmaf(C.C1[k], nz[u], C.Q[k] * silT));
    }
  }
}

// =================== launch ===================
extern "C" void kernel_launch(void* const* d_in, const int* in_sizes, int n_in,
                              void* d_out, int out_size) {
  const float* skes    = (const float*)d_in[0];  // (2,3,8,64,44)
  const float* sil_T   = (const float*)d_in[1];  // (16,1,64,44)
  const float* w_skes  = (const float*)d_in[2];  // (3,)
  const float* w_sil   = (const float*)d_in[3];  // ()
  const float* t_scale = (const float*)d_in[4];  // ()
  float* preds = (float*)d_out;                  // (1000,16,1,64,44)

  void* flagp = nullptr;
  cudaGetSymbolAddress(&flagp, g_flag);
  cudaMemsetAsync(flagp, 0, NSTEP * sizeof(int));   // reset flags each replay

  fused_kernel<<<NB_SOLVE + NB_NOISE, 256>>>(skes, sil_T, w_skes, w_sil, t_scale, preds);
}

// round 3
// speedup vs baseline: 1.7040x; 1.7040x over previous
#include <cuda_runtime.h>
#include <stdint.h>

#define NSTEP 1000
#define NELEM 45056      // 16*1*64*44
#define HW    2816       // 64*44
#define TPB   128        // 4 warps -> one per SMSP
#define NBLK  352        // 45056 / 128

// =================== compile-time schedule + folded keys ===================
struct alignas(16) F4 { float x, y, z, w; };
struct alignas(8)  U2 { unsigned x, y; };

struct SchedData {
  F4 sc[NSTEP + 1];   // {P, Q, C1, TCO}; padded entry for pipeline prefetch
  U2 key[NSTEP + 1];
};

constexpr double csqrt(double x) {
  double r = (x > 1.0) ? x : 1.0;
  for (int i = 0; i < 48; i++) r = 0.5 * (r + x / r);
  return r;
}
constexpr unsigned crotl(unsigned v, int r) { return (v << r) | (v >> (32 - r)); }
constexpr void ctf_round(unsigned& x0, unsigned& x1, int r) {
  x0 += x1; x1 = crotl(x1, r); x1 ^= x0;
}
constexpr void cthreefry(unsigned ks0, unsigned ks1, unsigned x0, unsigned x1,
                         unsigned& o0, unsigned& o1) {
  const unsigned ks2 = ks0 ^ ks1 ^ 0x1BD11BDAu;
  x0 += ks0; x1 += ks1;
  ctf_round(x0,x1,13); ctf_round(x0,x1,15); ctf_round(x0,x1,26); ctf_round(x0,x1,6);
  x0 += ks1; x1 += ks2 + 1u;
  ctf_round(x0,x1,17); ctf_round(x0,x1,29); ctf_round(x0,x1,16); ctf_round(x0,x1,24);
  x0 += ks2; x1 += ks0 + 2u;
  ctf_round(x0,x1,13); ctf_round(x0,x1,15); ctf_round(x0,x1,26); ctf_round(x0,x1,6);
  x0 += ks0; x1 += ks1 + 3u;
  ctf_round(x0,x1,17); ctf_round(x0,x1,29); ctf_round(x0,x1,16); ctf_round(x0,x1,24);
  x0 += ks1; x1 += ks2 + 4u;
  ctf_round(x0,x1,13); ctf_round(x0,x1,15); ctf_round(x0,x1,26); ctf_round(x0,x1,6);
  o0 = x0 + ks2;
  o1 = x1 + ks0 + 5u;
}

constexpr SchedData make_sched() {
  SchedData s{};
  double alph[NSTEP + 1] = {};
  alph[0] = 1.0;
  {
    double prod = 1.0;
    const double bstep = (0.02 - 1e-4) / 999.0;
    for (int i = 0; i < NSTEP; i++) {
      double beta = (i == 999) ? 0.02 : (1e-4 + (double)i * bstep);
      prod *= (1.0 - beta);
      alph[i + 1] = prod;
    }
  }
  for (int k = 0; k < NSTEP; k++) {
    const int idx = 999 - k;
    const float at  = (float)alph[idx + 1];
    const float atn = (float)alph[idx];            // k==999 -> 1.0
    const float a1  = 1.0f - at / atn;
    const float c1  = 0.1f * (float)csqrt((double)(a1 * (1.0f - atn) / (1.0f - at)));
    float t2 = 1.0f - atn - c1 * c1; if (t2 < 0.0f) t2 = 0.0f;
    const float c2  = (float)csqrt((double)t2);
    const double s1 = csqrt(1.0 - (double)at);
    const double Qd = (double)c2 / s1;                               // coeff of sil_T
    const double Pd = (double)(float)csqrt((double)atn)
                    - Qd * (double)(float)csqrt((double)at);         // coeff of sil_0
    s.sc[k].x = (float)Pd; s.sc[k].y = (float)Qd; s.sc[k].z = c1;
    s.sc[k].w = (float)idx / 1000.0f;
    unsigned k0 = 0, k1 = 0;
    cthreefry(0u, 42u, 0u, (unsigned)idx, k0, k1);   // fold_in(key(42), idx)
    s.key[k].x = k0; s.key[k].y = k1;
  }
  s.sc[NSTEP] = s.sc[NSTEP - 1];     // pipeline padding
  s.key[NSTEP] = s.key[NSTEP - 1];
  return s;
}

__device__ const SchedData d_sched = make_sched();

// =================== device threefry + normal ===================
__device__ __forceinline__ void tf_round(uint32_t& x0, uint32_t& x1, int r) {
  x0 += x1;
  x1 = __funnelshift_l(x1, x1, r);
  x1 ^= x0;
}
__device__ __forceinline__ uint32_t threefry_xored(uint32_t ks0, uint32_t ks1,
                                                   uint32_t ctr) {
  const uint32_t ks2 = ks0 ^ ks1 ^ 0x1BD11BDAu;
  uint32_t x0 = ks0, x1 = ctr + ks1;   // counter = (hi=0, lo=ctr)
  tf_round(x0,x1,13); tf_round(x0,x1,15); tf_round(x0,x1,26); tf_round(x0,x1,6);
  x0 += ks1; x1 += ks2 + 1u;
  tf_round(x0,x1,17); tf_round(x0,x1,29); tf_round(x0,x1,16); tf_round(x0,x1,24);
  x0 += ks2; x1 += ks0 + 2u;
  tf_round(x0,x1,13); tf_round(x0,x1,15); tf_round(x0,x1,26); tf_round(x0,x1,6);
  x0 += ks0; x1 += ks1 + 3u;
  tf_round(x0,x1,17); tf_round(x0,x1,29); tf_round(x0,x1,16); tf_round(x0,x1,24);
  x0 += ks1; x1 += ks2 + 4u;
  tf_round(x0,x1,13); tf_round(x0,x1,15); tf_round(x0,x1,26); tf_round(x0,x1,6);
  return (x0 + ks2) ^ (x1 + ks0 + 5u);   // out0 ^ out1 (partitionable mode)
}

__device__ __forceinline__ float bits_to_normal(uint32_t bits) {
  float f = __uint_as_float((bits >> 9) | 0x3f800000u) - 1.0f;  // [0,1)
  float u = fmaf(f, 2.0f, -0.99999994f);                        // (hi-lo) == 2.0f
  float w = -__logf(fmaf(-u, u, 1.0f));
  float p;
  if (w < 5.0f) {  // XLA ErfInv32 (Giles)
    w -= 2.5f;
    p =             2.81022636e-08f;
    p = fmaf(p, w,  3.43273939e-07f);
    p = fmaf(p, w, -3.5233877e-06f);
    p = fmaf(p, w, -4.39150654e-06f);
    p = fmaf(p, w,  0.00021858087f);
    p = fmaf(p, w, -0.00125372503f);
    p = fmaf(p, w, -0.00417768164f);
    p = fmaf(p, w,  0.246640727f);
    p = fmaf(p, w,  1.50140941f);
  } else {
    w = sqrtf(w) - 3.0f;
    p =            -0.000200214257f;
    p = fmaf(p, w,  0.000100950558f);
    p = fmaf(p, w,  0.00134934322f);
    p = fmaf(p, w, -0.00367342844f);
    p = fmaf(p, w,  0.00573950773f);
    p = fmaf(p, w, -0.0076224613f);
    p = fmaf(p, w,  0.00943887047f);
    p = fmaf(p, w,  1.00167406f);
    p = fmaf(p, w,  2.83297682f);
  }
  return 1.41421356f * (p * u);
}

// =================== fully fused kernel ===================
__global__ void __launch_bounds__(TPB) fused_all(
    const float* __restrict__ skes, const float* __restrict__ silT_g,
    const float* __restrict__ w_skes, const float* __restrict__ w_sil_p,
    const float* __restrict__ t_scale_p, float* __restrict__ preds)
{
  __shared__ F4 s_sc[NSTEP + 1];
  __shared__ U2 s_key[NSTEP + 1];
  for (int j = threadIdx.x; j < NSTEP + 1; j += TPB) {
    s_sc[j]  = d_sched.sc[j];
    s_key[j] = d_sched.key[j];
  }
  __syncthreads();

  const int i  = blockIdx.x * TPB + threadIdx.x;   // < 45056 exactly
  const int ns = i / HW;
  const int r  = i - ns * HW;
  const int n  = ns >> 3, sf = ns & 7;
  const float* bp = skes + (size_t)(n * 24 + sf) * HW + r;   // c stride = 8*HW
  const float cond = bp[0] * w_skes[0] + bp[8 * HW] * w_skes[1] + bp[16 * HW] * w_skes[2];
  const float silT = silT_g[i];
  const float wsil = *w_sil_p;
  const float tsc  = *t_scale_p;
  const uint32_t ctr = (uint32_t)i;

  float sil = silT;
  float nz = bits_to_normal(threefry_xored(s_key[0].x, s_key[0].y, ctr));
  float* op = preds + i;

#pragma unroll 2
  for (int k = 0; k < NSTEP; k++) {
    // pipeline: next step's noise (independent ALU chain, overlaps FMA solve)
    const U2 kk = s_key[k + 1];
    const float nz_next = bits_to_normal(threefry_xored(kk.x, kk.y, ctr));

    const F4 c = s_sc[k];
    const float z  = fmaf(wsil, sil, fmaf(tsc, c.w, cond));
    const float s0 = tanhf(z);
    op[(size_t)k * NELEM] = s0;
    sil = fmaf(c.x, s0, fmaf(c.z, nz, c.y * silT));
    nz = nz_next;
  }
}

// =================== launch ===================
extern "C" void kernel_launch(void* const* d_in, const int* in_sizes, int n_in,
                              void* d_out, int out_size) {
  const float* skes    = (const float*)d_in[0];  // (2,3,8,64,44)
  const float* sil_T   = (const float*)d_in[1];  // (16,1,64,44)
  const float* w_skes  = (const float*)d_in[2];  // (3,)
  const float* w_sil   = (const float*)d_in[3];  // ()
  const float* t_scale = (const float*)d_in[4];  // ()
  float* preds = (float*)d_out;                  // (1000,16,1,64,44)

  fused_all<<<NBLK, TPB>>>(skes, sil_T, w_skes, w_sil, t_scale, preds);
}

// round 4
// speedup vs baseline: 1.7812x; 1.0453x over previous
#include <cuda_runtime.h>
#include <stdint.h>

#define NSTEP 1000
#define NELEM 45056      // 16*1*64*44
#define HW    2816       // 64*44
#define TPB   64
#define NBLK  704        // 45056 / 64
#define GRP   4          // noise pipeline depth (steps per group)

// =================== compile-time schedule + folded keys ===================
struct alignas(16) F4 { float x, y, z, w; };
struct alignas(8)  U2 { unsigned x, y; };

struct SchedData {
  F4 sc[NSTEP + GRP];        // {P, Q, C1, TCO}; padded for pipeline prefetch
  U2 key[NSTEP + 2 * GRP];
};

constexpr double csqrt(double x) {
  double r = (x > 1.0) ? x : 1.0;
  for (int i = 0; i < 48; i++) r = 0.5 * (r + x / r);
  return r;
}
constexpr unsigned crotl(unsigned v, int r) { return (v << r) | (v >> (32 - r)); }
constexpr void ctf_round(unsigned& x0, unsigned& x1, int r) {
  x0 += x1; x1 = crotl(x1, r); x1 ^= x0;
}
constexpr void cthreefry(unsigned ks0, unsigned ks1, unsigned x0, unsigned x1,
                         unsigned& o0, unsigned& o1) {
  const unsigned ks2 = ks0 ^ ks1 ^ 0x1BD11BDAu;
  x0 += ks0; x1 += ks1;
  ctf_round(x0,x1,13); ctf_round(x0,x1,15); ctf_round(x0,x1,26); ctf_round(x0,x1,6);
  x0 += ks1; x1 += ks2 + 1u;
  ctf_round(x0,x1,17); ctf_round(x0,x1,29); ctf_round(x0,x1,16); ctf_round(x0,x1,24);
  x0 += ks2; x1 += ks0 + 2u;
  ctf_round(x0,x1,13); ctf_round(x0,x1,15); ctf_round(x0,x1,26); ctf_round(x0,x1,6);
  x0 += ks0; x1 += ks1 + 3u;
  ctf_round(x0,x1,17); ctf_round(x0,x1,29); ctf_round(x0,x1,16); ctf_round(x0,x1,24);
  x0 += ks1; x1 += ks2 + 4u;
  ctf_round(x0,x1,13); ctf_round(x0,x1,15); ctf_round(x0,x1,26); ctf_round(x0,x1,6);
  o0 = x0 + ks2;
  o1 = x1 + ks0 + 5u;
}

constexpr SchedData make_sched() {
  SchedData s{};
  double alph[NSTEP + 1] = {};
  alph[0] = 1.0;
  {
    double prod = 1.0;
    const double bstep = (0.02 - 1e-4) / 999.0;
    for (int i = 0; i < NSTEP; i++) {
      double beta = (i == 999) ? 0.02 : (1e-4 + (double)i * bstep);
      prod *= (1.0 - beta);
      alph[i + 1] = prod;
    }
  }
  for (int k = 0; k < NSTEP; k++) {
    const int idx = 999 - k;
    const float at  = (float)alph[idx + 1];
    const float atn = (float)alph[idx];            // k==999 -> 1.0
    const float a1  = 1.0f - at / atn;
    const float c1  = 0.1f * (float)csqrt((double)(a1 * (1.0f - atn) / (1.0f - at)));
    float t2 = 1.0f - atn - c1 * c1; if (t2 < 0.0f) t2 = 0.0f;
    const float c2  = (float)csqrt((double)t2);
    const double s1 = csqrt(1.0 - (double)at);
    const double Qd = (double)c2 / s1;                               // coeff of sil_T
    const double Pd = (double)(float)csqrt((double)atn)
                    - Qd * (double)(float)csqrt((double)at);         // coeff of sil_0
    s.sc[k].x = (float)Pd; s.sc[k].y = (float)Qd; s.sc[k].z = c1;
    s.sc[k].w = (float)idx / 1000.0f;
    unsigned k0 = 0, k1 = 0;
    cthreefry(0u, 42u, 0u, (unsigned)idx, k0, k1);   // fold_in(key(42), idx)
    s.key[k].x = k0; s.key[k].y = k1;
  }
  for (int k = NSTEP; k < NSTEP + GRP; k++)       s.sc[k]  = s.sc[NSTEP - 1];
  for (int k = NSTEP; k < NSTEP + 2 * GRP; k++)   s.key[k] = s.key[NSTEP - 1];
  return s;
}

__device__ const SchedData d_sched = make_sched();

// =================== device threefry + normal ===================
__device__ __forceinline__ void tf_round(uint32_t& x0, uint32_t& x1, int r) {
  x0 += x1;
  x1 = __funnelshift_l(x1, x1, r);
  x1 ^= x0;
}
__device__ __forceinline__ uint32_t threefry_xored(uint32_t ks0, uint32_t ks1,
                                                   uint32_t ctr) {
  const uint32_t ks2 = ks0 ^ ks1 ^ 0x1BD11BDAu;
  uint32_t x0 = ks0, x1 = ctr + ks1;   // counter = (hi=0, lo=ctr)
  tf_round(x0,x1,13); tf_round(x0,x1,15); tf_round(x0,x1,26); tf_round(x0,x1,6);
  x0 += ks1; x1 += ks2 + 1u;
  tf_round(x0,x1,17); tf_round(x0,x1,29); tf_round(x0,x1,16); tf_round(x0,x1,24);
  x0 += ks2; x1 += ks0 + 2u;
  tf_round(x0,x1,13); tf_round(x0,x1,15); tf_round(x0,x1,26); tf_round(x0,x1,6);
  x0 += ks0; x1 += ks1 + 3u;
  tf_round(x0,x1,17); tf_round(x0,x1,29); tf_round(x0,x1,16); tf_round(x0,x1,24);
  x0 += ks1; x1 += ks2 + 4u;
  tf_round(x0,x1,13); tf_round(x0,x1,15); tf_round(x0,x1,26); tf_round(x0,x1,6);
  return (x0 + ks2) ^ (x1 + ks0 + 5u);   // out0 ^ out1 (partitionable mode)
}

__device__ __forceinline__ float bits_to_normal(uint32_t bits) {
  float f = __uint_as_float((bits >> 9) | 0x3f800000u) - 1.0f;  // [0,1)
  float u = fmaf(f, 2.0f, -0.99999994f);                        // (hi-lo) == 2.0f
  float w = -__logf(fmaf(-u, u, 1.0f));
  float p;
  if (w < 5.0f) {  // XLA ErfInv32 (Giles)
    w -= 2.5f;
    p =             2.81022636e-08f;
    p = fmaf(p, w,  3.43273939e-07f);
    p = fmaf(p, w, -3.5233877e-06f);
    p = fmaf(p, w, -4.39150654e-06f);
    p = fmaf(p, w,  0.00021858087f);
    p = fmaf(p, w, -0.00125372503f);
    p = fmaf(p, w, -0.00417768164f);
    p = fmaf(p, w,  0.246640727f);
    p = fmaf(p, w,  1.50140941f);
  } else {
    w = sqrtf(w) - 3.0f;
    p =            -0.000200214257f;
    p = fmaf(p, w,  0.000100950558f);
    p = fmaf(p, w,  0.00134934322f);
    p = fmaf(p, w, -0.00367342844f);
    p = fmaf(p, w,  0.00573950773f);
    p = fmaf(p, w, -0.0076224613f);
    p = fmaf(p, w,  0.00943887047f);
    p = fmaf(p, w,  1.00167406f);
    p = fmaf(p, w,  2.83297682f);
  }
  return 1.41421356f * (p * u);
}

__device__ __forceinline__ float tanh_fast(float x) {
  float y;
  asm("tanh.approx.f32 %0, %1;" : "=f"(y) : "f"(x));
  return y;
}

// =================== fully fused kernel ===================
__global__ void __launch_bounds__(TPB) fused_all(
    const float* __restrict__ skes, const float* __restrict__ silT_g,
    const float* __restrict__ w_skes, const float* __restrict__ w_sil_p,
    const float* __restrict__ t_scale_p, float* __restrict__ preds)
{
  __shared__ F4 s_sc[NSTEP + GRP];
  __shared__ U2 s_key[NSTEP + 2 * GRP];
  for (int j = threadIdx.x; j < NSTEP + GRP; j += TPB)     s_sc[j]  = d_sched.sc[j];
  for (int j = threadIdx.x; j < NSTEP + 2 * GRP; j += TPB) s_key[j] = d_sched.key[j];
  __syncthreads();

  const int i  = blockIdx.x * TPB + threadIdx.x;   // < 45056 exactly
  const int ns = i / HW;
  const int r  = i - ns * HW;
  const int n  = ns >> 3, sf = ns & 7;
  const float* bp = skes + (size_t)(n * 24 + sf) * HW + r;   // c stride = 8*HW
  const float cond = bp[0] * w_skes[0] + bp[8 * HW] * w_skes[1] + bp[16 * HW] * w_skes[2];
  const float silT = silT_g[i];
  const float wsil = *w_sil_p;
  const float tsc  = *t_scale_p;
  const uint32_t ctr = (uint32_t)i;

  float sil = silT;
  float* op = preds + i;

  // prologue: noise for steps 0..GRP-1 (GRP independent chains)
  float nz[GRP];
#pragma unroll
  for (int j = 0; j < GRP; j++)
    nz[j] = bits_to_normal(threefry_xored(s_key[j].x, s_key[j].y, ctr));

#pragma unroll 1
  for (int g = 0; g < NSTEP; g += GRP) {
    // next group's noise: GRP independent ALU chains, overlap with solve below
    float nx[GRP];
#pragma unroll
    for (int j = 0; j < GRP; j++) {
      const U2 kk = s_key[g + GRP + j];
      nx[j] = bits_to_normal(threefry_xored(kk.x, kk.y, ctr));
    }
    // GRP sequential DDIM updates (short dependent chain via HW tanh)
#pragma unroll
    for (int u = 0; u < GRP; u++) {
      const F4 c = s_sc[g + u];
      const float z  = fmaf(wsil, sil, fmaf(tsc, c.w, cond));
      const float s0 = tanh_fast(z);
      op[(size_t)(g + u) * NELEM] = s0;
      sil = fmaf(c.x, s0, fmaf(c.z, nz[u], c.y * silT));
      nz[u] = nx[u];
    }
  }
}

// =================== launch ===================
extern "C" void kernel_launch(void* const* d_in, const int* in_sizes, int n_in,
                              void* d_out, int out_size) {
  const float* skes    = (const float*)d_in[0];  // (2,3,8,64,44)
  const float* sil_T   = (const float*)d_in[1];  // (16,1,64,44)
  const float* w_skes  = (const float*)d_in[2];  // (3,)
  const float* w_sil   = (const float*)d_in[3];  // ()
  const float* t_scale = (const float*)d_in[4];  // ()
  float* preds = (float*)d_out;                  // (1000,16,1,64,44)

  fused_all<<<NBLK, TPB>>>(skes, sil_T, w_skes, w_sil, t_scale, preds);
}

// round 5
// speedup vs baseline: 2.0835x; 1.1697x over previous
#include <cuda_runtime.h>
#include <stdint.h>

#define NSTEP 1000
#define NELEM 45056      // 16*1*64*44
#define HW    2816       // 64*44
#define TPB   64
#define NBLK  704        // 45056 / 64
#define GRP   4          // noise pipeline width (interleaved chains)

// =================== compile-time schedule + folded keys ===================
struct alignas(16) F4 { float x, y, z, w; };
struct alignas(16) U4 { unsigned x, y, z, w; };   // {ks0, ks1, ks2, unused}

struct SchedData {
  F4 sc[NSTEP + GRP];          // {P, Q, C1, TCO}; padded
  U4 key[NSTEP + 2 * GRP];     // {ks0, ks1, ks2, 0}; padded
};

constexpr double csqrt(double x) {
  double r = (x > 1.0) ? x : 1.0;
  for (int i = 0; i < 48; i++) r = 0.5 * (r + x / r);
  return r;
}
constexpr unsigned crotl(unsigned v, int r) { return (v << r) | (v >> (32 - r)); }
constexpr void ctf_round(unsigned& x0, unsigned& x1, int r) {
  x0 += x1; x1 = crotl(x1, r); x1 ^= x0;
}
constexpr void cthreefry(unsigned ks0, unsigned ks1, unsigned x0, unsigned x1,
                         unsigned& o0, unsigned& o1) {
  const unsigned ks2 = ks0 ^ ks1 ^ 0x1BD11BDAu;
  x0 += ks0; x1 += ks1;
  ctf_round(x0,x1,13); ctf_round(x0,x1,15); ctf_round(x0,x1,26); ctf_round(x0,x1,6);
  x0 += ks1; x1 += ks2 + 1u;
  ctf_round(x0,x1,17); ctf_round(x0,x1,29); ctf_round(x0,x1,16); ctf_round(x0,x1,24);
  x0 += ks2; x1 += ks0 + 2u;
  ctf_round(x0,x1,13); ctf_round(x0,x1,15); ctf_round(x0,x1,26); ctf_round(x0,x1,6);
  x0 += ks0; x1 += ks1 + 3u;
  ctf_round(x0,x1,17); ctf_round(x0,x1,29); ctf_round(x0,x1,16); ctf_round(x0,x1,24);
  x0 += ks1; x1 += ks2 + 4u;
  ctf_round(x0,x1,13); ctf_round(x0,x1,15); ctf_round(x0,x1,26); ctf_round(x0,x1,6);
  o0 = x0 + ks2;
  o1 = x1 + ks0 + 5u;
}

constexpr SchedData make_sched() {
  SchedData s{};
  double alph[NSTEP + 1] = {};
  alph[0] = 1.0;
  {
    double prod = 1.0;
    const double bstep = (0.02 - 1e-4) / 999.0;
    for (int i = 0; i < NSTEP; i++) {
      double beta = (i == 999) ? 0.02 : (1e-4 + (double)i * bstep);
      prod *= (1.0 - beta);
      alph[i + 1] = prod;
    }
  }
  for (int k = 0; k < NSTEP; k++) {
    const int idx = 999 - k;
    const float at  = (float)alph[idx + 1];
    const float atn = (float)alph[idx];            // k==999 -> 1.0
    const float a1  = 1.0f - at / atn;
    const float c1  = 0.1f * (float)csqrt((double)(a1 * (1.0f - atn) / (1.0f - at)));
    float t2 = 1.0f - atn - c1 * c1; if (t2 < 0.0f) t2 = 0.0f;
    const float c2  = (float)csqrt((double)t2);
    const double s1 = csqrt(1.0 - (double)at);
    const double Qd = (double)c2 / s1;                               // coeff of sil_T
    const double Pd = (double)(float)csqrt((double)atn)
                    - Qd * (double)(float)csqrt((double)at);         // coeff of sil_0
    s.sc[k].x = (float)Pd; s.sc[k].y = (float)Qd; s.sc[k].z = c1;
    s.sc[k].w = (float)idx / 1000.0f;
    unsigned k0 = 0, k1 = 0;
    cthreefry(0u, 42u, 0u, (unsigned)idx, k0, k1);   // fold_in(key(42), idx)
    s.key[k].x = k0; s.key[k].y = k1;
    s.key[k].z = k0 ^ k1 ^ 0x1BD11BDAu;
    s.key[k].w = 0u;
  }
  for (int k = NSTEP; k < NSTEP + GRP; k++)       s.sc[k]  = s.sc[NSTEP - 1];
  for (int k = NSTEP; k < NSTEP + 2 * GRP; k++)   s.key[k] = s.key[NSTEP - 1];
  return s;
}

__device__ const SchedData d_sched = make_sched();

__device__ __forceinline__ float tanh_fast(float x) {
  float y;
  asm("tanh.approx.f32 %0, %1;" : "=f"(y) : "f"(x));
  return y;
}

// =================== fully fused kernel ===================
__global__ void __launch_bounds__(TPB) fused_all(
    const float* __restrict__ skes, const float* __restrict__ silT_g,
    const float* __restrict__ w_skes, const float* __restrict__ w_sil_p,
    const float* __restrict__ t_scale_p, float* __restrict__ preds)
{
  __shared__ F4 s_sc[NSTEP + GRP];
  __shared__ U4 s_key[NSTEP + 2 * GRP];
  for (int j = threadIdx.x; j < NSTEP + GRP; j += TPB)     s_sc[j]  = d_sched.sc[j];
  for (int j = threadIdx.x; j < NSTEP + 2 * GRP; j += TPB) s_key[j] = d_sched.key[j];
  __syncthreads();

  const int i  = blockIdx.x * TPB + threadIdx.x;   // < 45056 exactly
  const int ns = i / HW;
  const int r  = i - ns * HW;
  const int n  = ns >> 3, sf = ns & 7;
  const float* bp = skes + (size_t)(n * 24 + sf) * HW + r;   // c stride = 8*HW
  const float cond = bp[0] * w_skes[0] + bp[8 * HW] * w_skes[1] + bp[16 * HW] * w_skes[2];
  const float silT = silT_g[i];
  const float wsil = *w_sil_p;
  const float tsc  = *t_scale_p;
  const uint32_t ctr = (uint32_t)i;

  float sil = silT;
  float* op = preds + i;

  // ---- 4-wide interleaved threefry (SoA) -> 4 normals ----
  uint32_t k0v[GRP], k1v[GRP], k2v[GRP];
  uint32_t x0[GRP], x1[GRP];
  float nz[GRP], nx[GRP];

#define TFR4(R)                                              \
  _Pragma("unroll") for (int j = 0; j < GRP; j++) {          \
    x0[j] += x1[j];                                          \
    x1[j] = __funnelshift_l(x1[j], x1[j], (R));              \
    x1[j] ^= x0[j];                                          \
  }

#define GEN4(BASE, DST)                                                     \
  {                                                                         \
    _Pragma("unroll") for (int j = 0; j < GRP; j++) {                       \
      const U4 kk = s_key[(BASE) + j];                                      \
      k0v[j] = kk.x; k1v[j] = kk.y; k2v[j] = kk.z;                          \
      x0[j] = k0v[j]; x1[j] = ctr + k1v[j];                                 \
    }                                                                       \
    TFR4(13) TFR4(15) TFR4(26) TFR4(6)                                      \
    _Pragma("unroll") for (int j = 0; j < GRP; j++) {                       \
      x0[j] += k1v[j]; x1[j] += k2v[j] + 1u;                                \
    }                                                                       \
    TFR4(17) TFR4(29) TFR4(16) TFR4(24)                                     \
    _Pragma("unroll") for (int j = 0; j < GRP; j++) {                       \
      x0[j] += k2v[j]; x1[j] += k0v[j] + 2u;                                \
    }                                                                       \
    TFR4(13) TFR4(15) TFR4(26) TFR4(6)                                      \
    _Pragma("unroll") for (int j = 0; j < GRP; j++) {                       \
      x0[j] += k0v[j]; x1[j] += k1v[j] + 3u;                                \
    }                                                                       \
    TFR4(17) TFR4(29) TFR4(16) TFR4(24)                                     \
    _Pragma("unroll") for (int j = 0; j < GRP; j++) {                       \
      x0[j] += k1v[j]; x1[j] += k2v[j] + 4u;                                \
    }                                                                       \
    TFR4(13) TFR4(15) TFR4(26) TFR4(6)                                      \
    float uu[GRP], ww[GRP];                                                 \
    _Pragma("unroll") for (int j = 0; j < GRP; j++) {                       \
      const uint32_t bits = (x0[j] + k2v[j]) ^ (x1[j] + k0v[j] + 5u);       \
      const float f = __uint_as_float((bits >> 9) | 0x3f800000u) - 1.0f;    \
      uu[j] = fmaf(f, 2.0f, -0.99999994f);                                  \
      ww[j] = -__logf(fmaf(-uu[j], uu[j], 1.0f));                           \
    }                                                                       \
    _Pragma("unroll") for (int j = 0; j < GRP; j++) {                       \
      float w = ww[j], p;                                                   \
      if (w < 5.0f) {                                                       \
        w -= 2.5f;                                                          \
        p =             2.81022636e-08f;                                    \
        p = fmaf(p, w,  3.43273939e-07f);                                   \
        p = fmaf(p, w, -3.5233877e-06f);                                    \
        p = fmaf(p, w, -4.39150654e-06f);                                   \
        p = fmaf(p, w,  0.00021858087f);                                    \
        p = fmaf(p, w, -0.00125372503f);                                    \
        p = fmaf(p, w, -0.00417768164f);                                    \
        p = fmaf(p, w,  0.246640727f);                                      \
        p = fmaf(p, w,  1.50140941f);                                       \
      } else {                                                              \
        w = sqrtf(w) - 3.0f;                                                \
        p =            -0.000200214257f;                                    \
        p = fmaf(p, w,  0.000100950558f);                                   \
        p = fmaf(p, w,  0.00134934322f);                                    \
        p = fmaf(p, w, -0.00367342844f);                                    \
        p = fmaf(p, w,  0.00573950773f);                                    \
        p = fmaf(p, w, -0.0076224613f);                                     \
        p = fmaf(p, w,  0.00943887047f);                                    \
        p = fmaf(p, w,  1.00167406f);                                       \
        p = fmaf(p, w,  2.83297682f);                                       \
      }                                                                     \
      DST[j] = 1.41421356f * (p * uu[j]);                                   \
    }                                                                       \
  }

  GEN4(0, nz)   // prologue: steps 0..3

#pragma unroll 1
  for (int g = 0; g < NSTEP; g += GRP) {
    GEN4(g + GRP, nx)   // next group's noise, 4 interleaved chains
#pragma unroll
    for (int u = 0; u < GRP; u++) {
      const F4 c = s_sc[g + u];
      const float z  = fmaf(wsil, sil, fmaf(tsc, c.w, cond));
      const float s0 = tanh_fast(z);
      op[(size_t)(g + u) * NELEM] = s0;
      sil = fmaf(c.x, s0, fmaf(c.z, nz[u], c.y * silT));
      nz[u] = nx[u];
    }
  }
#undef GEN4
#undef TFR4
}

// =================== launch ===================
extern "C" void kernel_launch(void* const* d_in, const int* in_sizes, int n_in,
                              void* d_out, int out_size) {
  const float* skes    = (const float*)d_in[0];  // (2,3,8,64,44)
  const float* sil_T   = (const float*)d_in[1];  // (16,1,64,44)
  const float* w_skes  = (const float*)d_in[2];  // (3,)
  const float* w_sil   = (const float*)d_in[3];  // ()
  const float* t_scale = (const float*)d_in[4];  // ()
  float* preds = (float*)d_out;                  // (1000,16,1,64,44)

  fused_all<<<NBLK, TPB>>>(skes, sil_T, w_skes, w_sil, t_scale, preds);
}

// round 6
// speedup vs baseline: 2.1930x; 1.0525x over previous
#include <cuda_runtime.h>
#include <stdint.h>

#define NSTEP  1000
#define NELEM  45056     // 16*1*64*44
#define HW     2816      // 64*44
#define EPB    64        // elements per block
#define TPB    256       // 2 solver warps + 6 producer warps
#define NBLK   704       // 45056 / 64
#define CSTEP  40        // steps per chunk
#define NCHUNK 25        // 1000 / 40
#define SPC    (CSTEP * EPB)   // samples per chunk = 2560

// =================== compile-time schedule + folded keys ===================
struct alignas(16) F4 { float x, y, z, w; };
struct alignas(16) U4 { unsigned x, y, z, w; };   // {ks0, ks1, ks2, 0}

struct SchedData {
  F4 sc[NSTEP];     // {P, Q, C1, TCO}
  U4 key[NSTEP];    // {ks0, ks1, ks2, 0}
};

constexpr double csqrt(double x) {
  double r = (x > 1.0) ? x : 1.0;
  for (int i = 0; i < 48; i++) r = 0.5 * (r + x / r);
  return r;
}
constexpr unsigned crotl(unsigned v, int r) { return (v << r) | (v >> (32 - r)); }
constexpr void ctf_round(unsigned& x0, unsigned& x1, int r) {
  x0 += x1; x1 = crotl(x1, r); x1 ^= x0;
}
constexpr void cthreefry(unsigned ks0, unsigned ks1, unsigned x0, unsigned x1,
                         unsigned& o0, unsigned& o1) {
  const unsigned ks2 = ks0 ^ ks1 ^ 0x1BD11BDAu;
  x0 += ks0; x1 += ks1;
  ctf_round(x0,x1,13); ctf_round(x0,x1,15); ctf_round(x0,x1,26); ctf_round(x0,x1,6);
  x0 += ks1; x1 += ks2 + 1u;
  ctf_round(x0,x1,17); ctf_round(x0,x1,29); ctf_round(x0,x1,16); ctf_round(x0,x1,24);
  x0 += ks2; x1 += ks0 + 2u;
  ctf_round(x0,x1,13); ctf_round(x0,x1,15); ctf_round(x0,x1,26); ctf_round(x0,x1,6);
  x0 += ks0; x1 += ks1 + 3u;
  ctf_round(x0,x1,17); ctf_round(x0,x1,29); ctf_round(x0,x1,16); ctf_round(x0,x1,24);
  x0 += ks1; x1 += ks2 + 4u;
  ctf_round(x0,x1,13); ctf_round(x0,x1,15); ctf_round(x0,x1,26); ctf_round(x0,x1,6);
  o0 = x0 + ks2;
  o1 = x1 + ks0 + 5u;
}

constexpr SchedData make_sched() {
  SchedData s{};
  double alph[NSTEP + 1] = {};
  alph[0] = 1.0;
  {
    double prod = 1.0;
    const double bstep = (0.02 - 1e-4) / 999.0;
    for (int i = 0; i < NSTEP; i++) {
      double beta = (i == 999) ? 0.02 : (1e-4 + (double)i * bstep);
      prod *= (1.0 - beta);
      alph[i + 1] = prod;
    }
  }
  for (int k = 0; k < NSTEP; k++) {
    const int idx = 999 - k;
    const float at  = (float)alph[idx + 1];
    const float atn = (float)alph[idx];            // k==999 -> 1.0
    const float a1  = 1.0f - at / atn;
    const float c1  = 0.1f * (float)csqrt((double)(a1 * (1.0f - atn) / (1.0f - at)));
    float t2 = 1.0f - atn - c1 * c1; if (t2 < 0.0f) t2 = 0.0f;
    const float c2  = (float)csqrt((double)t2);
    const double s1 = csqrt(1.0 - (double)at);
    const double Qd = (double)c2 / s1;                               // coeff of sil_T
    const double Pd = (double)(float)csqrt((double)atn)
                    - Qd * (double)(float)csqrt((double)at);         // coeff of sil_0
    s.sc[k].x = (float)Pd; s.sc[k].y = (float)Qd; s.sc[k].z = c1;
    s.sc[k].w = (float)idx / 1000.0f;
    unsigned k0 = 0, k1 = 0;
    cthreefry(0u, 42u, 0u, (unsigned)idx, k0, k1);   // fold_in(key(42), idx)
    s.key[k].x = k0; s.key[k].y = k1;
    s.key[k].z = k0 ^ k1 ^ 0x1BD11BDAu;
    s.key[k].w = 0u;
  }
  return s;
}

__constant__ SchedData c_sched = make_sched();

// =================== device threefry + normal ===================
__device__ __forceinline__ void tf_round(uint32_t& x0, uint32_t& x1, int r) {
  x0 += x1;
  x1 = __funnelshift_l(x1, x1, r);
  x1 ^= x0;
}

__device__ __forceinline__ float gen_normal(U4 kk, uint32_t ctr) {
  const uint32_t ks0 = kk.x, ks1 = kk.y, ks2 = kk.z;
  uint32_t x0 = ks0, x1 = ctr + ks1;
  tf_round(x0,x1,13); tf_round(x0,x1,15); tf_round(x0,x1,26); tf_round(x0,x1,6);
  x0 += ks1; x1 += ks2 + 1u;
  tf_round(x0,x1,17); tf_round(x0,x1,29); tf_round(x0,x1,16); tf_round(x0,x1,24);
  x0 += ks2; x1 += ks0 + 2u;
  tf_round(x0,x1,13); tf_round(x0,x1,15); tf_round(x0,x1,26); tf_round(x0,x1,6);
  x0 += ks0; x1 += ks1 + 3u;
  tf_round(x0,x1,17); tf_round(x0,x1,29); tf_round(x0,x1,16); tf_round(x0,x1,24);
  x0 += ks1; x1 += ks2 + 4u;
  tf_round(x0,x1,13); tf_round(x0,x1,15); tf_round(x0,x1,26); tf_round(x0,x1,6);
  const uint32_t bits = (x0 + ks2) ^ (x1 + ks0 + 5u);   // partitionable mode

  const float f = __uint_as_float((bits >> 9) | 0x3f800000u) - 1.0f;  // [0,1)
  const float u = fmaf(f, 2.0f, -0.99999994f);
  float w = -__logf(fmaf(-u, u, 1.0f));
  float p;
  if (w < 5.0f) {  // XLA ErfInv32 (Giles)
    w -= 2.5f;
    p =             2.81022636e-08f;
    p = fmaf(p, w,  3.43273939e-07f);
    p = fmaf(p, w, -3.5233877e-06f);
    p = fmaf(p, w, -4.39150654e-06f);
    p = fmaf(p, w,  0.00021858087f);
    p = fmaf(p, w, -0.00125372503f);
    p = fmaf(p, w, -0.00417768164f);
    p = fmaf(p, w,  0.246640727f);
    p = fmaf(p, w,  1.50140941f);
  } else {
    w = sqrtf(w) - 3.0f;
    p =            -0.000200214257f;
    p = fmaf(p, w,  0.000100950558f);
    p = fmaf(p, w,  0.00134934322f);
    p = fmaf(p, w, -0.00367342844f);
    p = fmaf(p, w,  0.00573950773f);
    p = fmaf(p, w, -0.0076224613f);
    p = fmaf(p, w,  0.00943887047f);
    p = fmaf(p, w,  1.00167406f);
    p = fmaf(p, w,  2.83297682f);
  }
  return 1.41421356f * (p * u);
}

__device__ __forceinline__ float tanh_fast(float x) {
  float y;
  asm("tanh.approx.f32 %0, %1;" : "=f"(y) : "f"(x));
  return y;
}

// =================== fused producer/consumer-in-block kernel ===================
__global__ void __launch_bounds__(TPB, 5) fused_all(
    const float* __restrict__ skes, const float* __restrict__ silT_g,
    const float* __restrict__ w_skes, const float* __restrict__ w_sil_p,
    const float* __restrict__ t_scale_p, float* __restrict__ preds)
{
  __shared__ U4    s_key[NSTEP];
  __shared__ float s_buf[2][CSTEP][EPB];

  const int tid = threadIdx.x;
  for (int j = tid; j < NSTEP; j += TPB) s_key[j] = c_sched.key[j];

  const int base = blockIdx.x * EPB;

  // solver-only state (tid < EPB)
  float sil = 0.f, silT = 0.f, cond = 0.f, wsil = 0.f, tsc = 0.f;
  if (tid < EPB) {
    const int i  = base + tid;
    const int ns = i / HW;
    const int r  = i - ns * HW;
    const int n  = ns >> 3, sf = ns & 7;
    const float* bp = skes + (size_t)(n * 24 + sf) * HW + r;   // c stride = 8*HW
    cond = bp[0] * w_skes[0] + bp[8 * HW] * w_skes[1] + bp[16 * HW] * w_skes[2];
    silT = silT_g[i];
    wsil = *w_sil_p;
    tsc  = *t_scale_p;
    sil  = silT;
  }
  __syncthreads();

  // ---- prologue: all 256 threads produce chunk 0 (10 samples each) ----
#pragma unroll 2
  for (int j = 0; j < SPC / TPB; j++) {
    const int idx = tid + j * TPB;
    const int s = idx >> 6, e = idx & 63;
    s_buf[0][s][e] = gen_normal(s_key[s], (uint32_t)(base + e));
  }
  __syncthreads();

  // ---- main loop: 25 chunks ----
  for (int g = 0; g < NCHUNK; g++) {
    const int cb = g & 1, nb = cb ^ 1;

    if (g < NCHUNK - 1) {
      const int kbase = (g + 1) * CSTEP;
      if (tid < EPB) {
        // solver threads: light production quota (7 samples)
#pragma unroll 2
        for (int j = 0; j < 7; j++) {
          const int idx = tid * 7 + j;            // [0, 448)
          const int s = idx >> 6, e = idx & 63;
          s_buf[nb][s][e] = gen_normal(s_key[kbase + s], (uint32_t)(base + e));
        }
      } else {
        // producer threads: 11 samples
#pragma unroll 2
        for (int j = 0; j < 11; j++) {
          const int idx = 448 + (tid - EPB) * 11 + j;   // [448, 2560)
          const int s = idx >> 6, e = idx & 63;
          s_buf[nb][s][e] = gen_normal(s_key[kbase + s], (uint32_t)(base + e));
        }
      }
    }

    if (tid < EPB) {
      // consume current chunk: 40 sequential DDIM steps
      float* op = preds + (size_t)(g * CSTEP) * NELEM + base + tid;
#pragma unroll 4
      for (int u = 0; u < CSTEP; u++) {
        const F4 c = c_sched.sc[g * CSTEP + u];   // uniform -> const cache
        const float z  = fmaf(wsil, sil, fmaf(tsc, c.w, cond));
        const float s0 = tanh_fast(z);
        op[(size_t)u * NELEM] = s0;
        sil = fmaf(c.x, s0, fmaf(c.z, s_buf[cb][u][tid], c.y * silT));
      }
    }
    __syncthreads();
  }
}

// =================== launch ===================
extern "C" void kernel_launch(void* const* d_in, const int* in_sizes, int n_in,
                              void* d_out, int out_size) {
  const float* skes    = (const float*)d_in[0];  // (2,3,8,64,44)
  const float* sil_T   = (const float*)d_in[1];  // (16,1,64,44)
  const float* w_skes  = (const float*)d_in[2];  // (3,)
  const float* w_sil   = (const float*)d_in[3];  // ()
  const float* t_scale = (const float*)d_in[4];  // ()
  float* preds = (float*)d_out;                  // (1000,16,1,64,44)

  fused_all<<<NBLK, TPB>>>(skes, sil_T, w_skes, w_sil, t_scale, preds);
}

// round 7
// speedup vs baseline: 2.3186x; 1.0573x over previous
#include <cuda_runtime.h>
#include <stdint.h>

#define NSTEP  1000
#define NELEM  45056     // 16*1*64*44
#define HW     2816      // 64*44
#define EPB    64        // elements per block
#define TPB    256       // pair 0 = solver warps, pairs 1-3 = producers
#define NBLK   704       // 45056 / 64
#define CSTEP  50        // steps per chunk
#define NCHUNK 20        // 1000 / 50
#define SOLV_STEPS 8     // solver pair production quota (4 pair-gens)
#define PROD_STEPS 14    // producer pair quota (7 pair-gens); 8+3*14=50

// =================== compile-time schedule + folded keys ===================
struct alignas(16) F4 { float x, y, z, w; };
struct alignas(16) U4 { unsigned x, y, z, w; };   // {ks0, ks1, ks2, 0}

struct SchedData {
  F4 sc[NSTEP];     // {P, Q, C1, TCO}
  U4 key[NSTEP];    // {ks0, ks1, ks2, 0}
};

constexpr double csqrt(double x) {
  double r = (x > 1.0) ? x : 1.0;
  for (int i = 0; i < 48; i++) r = 0.5 * (r + x / r);
  return r;
}
constexpr unsigned crotl(unsigned v, int r) { return (v << r) | (v >> (32 - r)); }
constexpr void ctf_round(unsigned& x0, unsigned& x1, int r) {
  x0 += x1; x1 = crotl(x1, r); x1 ^= x0;
}
constexpr void cthreefry(unsigned ks0, unsigned ks1, unsigned x0, unsigned x1,
                         unsigned& o0, unsigned& o1) {
  const unsigned ks2 = ks0 ^ ks1 ^ 0x1BD11BDAu;
  x0 += ks0; x1 += ks1;
  ctf_round(x0,x1,13); ctf_round(x0,x1,15); ctf_round(x0,x1,26); ctf_round(x0,x1,6);
  x0 += ks1; x1 += ks2 + 1u;
  ctf_round(x0,x1,17); ctf_round(x0,x1,29); ctf_round(x0,x1,16); ctf_round(x0,x1,24);
  x0 += ks2; x1 += ks0 + 2u;
  ctf_round(x0,x1,13); ctf_round(x0,x1,15); ctf_round(x0,x1,26); ctf_round(x0,x1,6);
  x0 += ks0; x1 += ks1 + 3u;
  ctf_round(x0,x1,17); ctf_round(x0,x1,29); ctf_round(x0,x1,16); ctf_round(x0,x1,24);
  x0 += ks1; x1 += ks2 + 4u;
  ctf_round(x0,x1,13); ctf_round(x0,x1,15); ctf_round(x0,x1,26); ctf_round(x0,x1,6);
  o0 = x0 + ks2;
  o1 = x1 + ks0 + 5u;
}

constexpr SchedData make_sched() {
  SchedData s{};
  double alph[NSTEP + 1] = {};
  alph[0] = 1.0;
  {
    double prod = 1.0;
    const double bstep = (0.02 - 1e-4) / 999.0;
    for (int i = 0; i < NSTEP; i++) {
      double beta = (i == 999) ? 0.02 : (1e-4 + (double)i * bstep);
      prod *= (1.0 - beta);
      alph[i + 1] = prod;
    }
  }
  for (int k = 0; k < NSTEP; k++) {
    const int idx = 999 - k;
    const float at  = (float)alph[idx + 1];
    const float atn = (float)alph[idx];            // k==999 -> 1.0
    const float a1  = 1.0f - at / atn;
    const float c1  = 0.1f * (float)csqrt((double)(a1 * (1.0f - atn) / (1.0f - at)));
    float t2 = 1.0f - atn - c1 * c1; if (t2 < 0.0f) t2 = 0.0f;
    const float c2  = (float)csqrt((double)t2);
    const double s1 = csqrt(1.0 - (double)at);
    const double Qd = (double)c2 / s1;                               // coeff of sil_T
    const double Pd = (double)(float)csqrt((double)atn)
                    - Qd * (double)(float)csqrt((double)at);         // coeff of sil_0
    s.sc[k].x = (float)Pd; s.sc[k].y = (float)Qd; s.sc[k].z = c1;
    s.sc[k].w = (float)idx / 1000.0f;
    unsigned k0 = 0, k1 = 0;
    cthreefry(0u, 42u, 0u, (unsigned)idx, k0, k1);   // fold_in(key(42), idx)
    s.key[k].x = k0; s.key[k].y = k1;
    s.key[k].z = k0 ^ k1 ^ 0x1BD11BDAu;
    s.key[k].w = 0u;
  }
  return s;
}

__constant__ SchedData c_sched = make_sched();

// =================== 2-wide interleaved threefry -> 2 normals ===================
// Keys come from smem (warp-uniform broadcast); ctr fixed per thread.
__device__ __forceinline__ void gen_normal2(const U4* __restrict__ kk2,
                                            uint32_t ctr, float* out) {
  uint32_t k0[2], k1[2], k2[2], x0[2], x1[2];
#pragma unroll
  for (int j = 0; j < 2; j++) {
    const U4 kk = kk2[j];
    k0[j] = kk.x; k1[j] = kk.y; k2[j] = kk.z;
    x0[j] = k0[j]; x1[j] = ctr + k1[j];
  }
#define R2(RR)                                         \
  _Pragma("unroll") for (int j = 0; j < 2; j++) {      \
    x0[j] += x1[j];                                    \
    x1[j] = __funnelshift_l(x1[j], x1[j], (RR));       \
    x1[j] ^= x0[j];                                    \
  }
  R2(13) R2(15) R2(26) R2(6)
#pragma unroll
  for (int j = 0; j < 2; j++) { x0[j] += k1[j]; x1[j] += k2[j] + 1u; }
  R2(17) R2(29) R2(16) R2(24)
#pragma unroll
  for (int j = 0; j < 2; j++) { x0[j] += k2[j]; x1[j] += k0[j] + 2u; }
  R2(13) R2(15) R2(26) R2(6)
#pragma unroll
  for (int j = 0; j < 2; j++) { x0[j] += k0[j]; x1[j] += k1[j] + 3u; }
  R2(17) R2(29) R2(16) R2(24)
#pragma unroll
  for (int j = 0; j < 2; j++) { x0[j] += k1[j]; x1[j] += k2[j] + 4u; }
  R2(13) R2(15) R2(26) R2(6)
#undef R2
  float uu[2], ww[2];
#pragma unroll
  for (int j = 0; j < 2; j++) {
    const uint32_t bits = (x0[j] + k2[j]) ^ (x1[j] + k0[j] + 5u);   // o0 ^ o1
    const float f = __uint_as_float((bits >> 9) | 0x3f800000u) - 1.0f;
    uu[j] = fmaf(f, 2.0f, -0.99999994f);
    ww[j] = -__logf(fmaf(-uu[j], uu[j], 1.0f));
  }
#pragma unroll
  for (int j = 0; j < 2; j++) {
    float w = ww[j], p;
    if (w < 5.0f) {  // XLA ErfInv32 (Giles)
      w -= 2.5f;
      p =             2.81022636e-08f;
      p = fmaf(p, w,  3.43273939e-07f);
      p = fmaf(p, w, -3.5233877e-06f);
      p = fmaf(p, w, -4.39150654e-06f);
      p = fmaf(p, w,  0.00021858087f);
      p = fmaf(p, w, -0.00125372503f);
      p = fmaf(p, w, -0.00417768164f);
      p = fmaf(p, w,  0.246640727f);
      p = fmaf(p, w,  1.50140941f);
    } else {
      w = sqrtf(w) - 3.0f;
      p =            -0.000200214257f;
      p = fmaf(p, w,  0.000100950558f);
      p = fmaf(p, w,  0.00134934322f);
      p = fmaf(p, w, -0.00367342844f);
      p = fmaf(p, w,  0.00573950773f);
      p = fmaf(p, w, -0.0076224613f);
      p = fmaf(p, w,  0.00943887047f);
      p = fmaf(p, w,  1.00167406f);
      p = fmaf(p, w,  2.83297682f);
    }
    out[j] = 1.41421356f * (p * uu[j]);
  }
}

__device__ __forceinline__ float tanh_fast(float x) {
  float y;
  asm("tanh.approx.f32 %0, %1;" : "=f"(y) : "f"(x));
  return y;
}

// =================== fused producer/consumer-in-block kernel ===================
__global__ void __launch_bounds__(TPB, 5) fused_all(
    const float* __restrict__ skes, const float* __restrict__ silT_g,
    const float* __restrict__ w_skes, const float* __restrict__ w_sil_p,
    const float* __restrict__ t_scale_p, float* __restrict__ preds)
{
  __shared__ U4    s_key[NSTEP];
  __shared__ float s_buf[2][CSTEP][EPB];

  const int tid  = threadIdx.x;
  const int e    = tid & 63;     // fixed element within block
  const int pair = tid >> 6;     // 0 = solver pair, 1..3 = producer pairs
  const int base = blockIdx.x * EPB;
  const uint32_t ctr = (uint32_t)(base + e);

  for (int j = tid; j < NSTEP; j += TPB) s_key[j] = c_sched.key[j];

  // solver-only state (tid < EPB)
  float sil = 0.f, silT = 0.f, cond = 0.f, wsil = 0.f, tsc = 0.f;
  if (tid < EPB) {
    const int i  = base + tid;
    const int ns = i / HW;
    const int r  = i - ns * HW;
    const int n  = ns >> 3, sf = ns & 7;
    const float* bp = skes + (size_t)(n * 24 + sf) * HW + r;   // c stride = 8*HW
    cond = bp[0] * w_skes[0] + bp[8 * HW] * w_skes[1] + bp[16 * HW] * w_skes[2];
    silT = silT_g[i];
    wsil = *w_sil_p;
    tsc  = *t_scale_p;
    sil  = silT;
  }
  __syncthreads();

  // ---- prologue: chunk 0 (25 step-pairs over 4 warp-pairs) ----
  for (int ps = pair; ps < CSTEP / 2; ps += 4) {
    float o[2];
    gen_normal2(&s_key[2 * ps], ctr, o);
    s_buf[0][2 * ps][e]     = o[0];
    s_buf[0][2 * ps + 1][e] = o[1];
  }
  __syncthreads();

  // ---- main loop: 20 chunks ----
  for (int g = 0; g < NCHUNK; g++) {
    const int cb = g & 1, nb = cb ^ 1;

    if (g < NCHUNK - 1) {
      const int kb = (g + 1) * CSTEP;
      if (pair == 0) {
        // solver pair: steps [0, 8) of next chunk
#pragma unroll
        for (int jp = 0; jp < SOLV_STEPS / 2; jp++) {
          const int s = 2 * jp;
          float o[2];
          gen_normal2(&s_key[kb + s], ctr, o);
          s_buf[nb][s][e]     = o[0];
          s_buf[nb][s + 1][e] = o[1];
        }
      } else {
        // producer pair p: steps [8 + 14(p-1), 8 + 14p)
        const int sbase = SOLV_STEPS + (pair - 1) * PROD_STEPS;
#pragma unroll
        for (int jp = 0; jp < PROD_STEPS / 2; jp++) {
          const int s = sbase + 2 * jp;
          float o[2];
          gen_normal2(&s_key[kb + s], ctr, o);
          s_buf[nb][s][e]     = o[0];
          s_buf[nb][s + 1][e] = o[1];
        }
      }
    }

    if (tid < EPB) {
      // consume current chunk: 50 sequential DDIM steps
      float* op = preds + (size_t)(g * CSTEP) * NELEM + base + tid;
#pragma unroll 5
      for (int u = 0; u < CSTEP; u++) {
        const F4 c = c_sched.sc[g * CSTEP + u];   // uniform -> const cache
        const float z  = fmaf(wsil, sil, fmaf(tsc, c.w, cond));
        const float s0 = tanh_fast(z);
        op[(size_t)u * NELEM] = s0;
        sil = fmaf(c.x, s0, fmaf(c.z, s_buf[cb][u][tid], c.y * silT));
      }
    }
    __syncthreads();
  }
}

// =================== launch ===================
extern "C" void kernel_launch(void* const* d_in, const int* in_sizes, int n_in,
                              void* d_out, int out_size) {
  const float* skes    = (const float*)d_in[0];  // (2,3,8,64,44)
  const float* sil_T   = (const float*)d_in[1];  // (16,1,64,44)
  const float* w_skes  = (const float*)d_in[2];  // (3,)
  const float* w_sil   = (const float*)d_in[3];  // ()
  const float* t_scale = (const float*)d_in[4];  // ()
  float* preds = (float*)d_out;                  // (1000,16,1,64,44)

  fused_all<<<NBLK, TPB>>>(skes, sil_T, w_skes, w_sil, t_scale, preds);
}

// round 8
// speedup vs baseline: 2.3377x; 1.0082x over previous
#include <cuda_runtime.h>
#include <stdint.h>

#define NSTEP  1000
#define NELEM  45056     // 16*1*64*44
#define HW     2816      // 64*44
#define EPB    64        // elements per block
#define TPB    256       // warps 0-1 solver(+1 prod step each), 2-7 producers
#define NBLK   704       // 45056 / 64
#define CSTEP  50        // steps per chunk
#define NCHUNK 20        // 1000 / 50

// =================== compile-time schedule + folded keys ===================
struct alignas(16) F4 { float x, y, z, w; };
struct alignas(16) U4 { unsigned x, y, z, w; };   // {ks0, ks1, ks2, 0}

struct SchedData {
  F4 sc[NSTEP];     // {P, Q, C1, TCO}
  U4 key[NSTEP];    // {ks0, ks1, ks2, 0}
};

constexpr double csqrt(double x) {
  double r = (x > 1.0) ? x : 1.0;
  for (int i = 0; i < 48; i++) r = 0.5 * (r + x / r);
  return r;
}
constexpr unsigned crotl(unsigned v, int r) { return (v << r) | (v >> (32 - r)); }
constexpr void ctf_round(unsigned& x0, unsigned& x1, int r) {
  x0 += x1; x1 = crotl(x1, r); x1 ^= x0;
}
constexpr void cthreefry(unsigned ks0, unsigned ks1, unsigned x0, unsigned x1,
                         unsigned& o0, unsigned& o1) {
  const unsigned ks2 = ks0 ^ ks1 ^ 0x1BD11BDAu;
  x0 += ks0; x1 += ks1;
  ctf_round(x0,x1,13); ctf_round(x0,x1,15); ctf_round(x0,x1,26); ctf_round(x0,x1,6);
  x0 += ks1; x1 += ks2 + 1u;
  ctf_round(x0,x1,17); ctf_round(x0,x1,29); ctf_round(x0,x1,16); ctf_round(x0,x1,24);
  x0 += ks2; x1 += ks0 + 2u;
  ctf_round(x0,x1,13); ctf_round(x0,x1,15); ctf_round(x0,x1,26); ctf_round(x0,x1,6);
  x0 += ks0; x1 += ks1 + 3u;
  ctf_round(x0,x1,17); ctf_round(x0,x1,29); ctf_round(x0,x1,16); ctf_round(x0,x1,24);
  x0 += ks1; x1 += ks2 + 4u;
  ctf_round(x0,x1,13); ctf_round(x0,x1,15); ctf_round(x0,x1,26); ctf_round(x0,x1,6);
  o0 = x0 + ks2;
  o1 = x1 + ks0 + 5u;
}

constexpr SchedData make_sched() {
  SchedData s{};
  double alph[NSTEP + 1] = {};
  alph[0] = 1.0;
  {
    double prod = 1.0;
    const double bstep = (0.02 - 1e-4) / 999.0;
    for (int i = 0; i < NSTEP; i++) {
      double beta = (i == 999) ? 0.02 : (1e-4 + (double)i * bstep);
      prod *= (1.0 - beta);
      alph[i + 1] = prod;
    }
  }
  for (int k = 0; k < NSTEP; k++) {
    const int idx = 999 - k;
    const float at  = (float)alph[idx + 1];
    const float atn = (float)alph[idx];            // k==999 -> 1.0
    const float a1  = 1.0f - at / atn;
    const float c1  = 0.1f * (float)csqrt((double)(a1 * (1.0f - atn) / (1.0f - at)));
    float t2 = 1.0f - atn - c1 * c1; if (t2 < 0.0f) t2 = 0.0f;
    const float c2  = (float)csqrt((double)t2);
    const double s1 = csqrt(1.0 - (double)at);
    const double Qd = (double)c2 / s1;                               // coeff of sil_T
    const double Pd = (double)(float)csqrt((double)atn)
                    - Qd * (double)(float)csqrt((double)at);         // coeff of sil_0
    s.sc[k].x = (float)Pd; s.sc[k].y = (float)Qd; s.sc[k].z = c1;
    s.sc[k].w = (float)idx / 1000.0f;
    unsigned k0 = 0, k1 = 0;
    cthreefry(0u, 42u, 0u, (unsigned)idx, k0, k1);   // fold_in(key(42), idx)
    s.key[k].x = k0; s.key[k].y = k1;
    s.key[k].z = k0 ^ k1 ^ 0x1BD11BDAu;
    s.key[k].w = 0u;
  }
  return s;
}

__constant__ SchedData c_sched = make_sched();

// =================== 2-element interleaved threefry -> 2 normals ===================
// RS: classic SHF rotate (alu pipe).  RM: IMAD.WIDE rotate + 3-input LOP3
// (rotl halves are bit-disjoint -> lo^hi == rotl; fold the ^x0 into one LOP3).
#define RS(RR)                                                        \
  _Pragma("unroll") for (int j = 0; j < 2; j++) {                     \
    x0[j] += x1[j];                                                   \
    x1[j] = __funnelshift_l(x1[j], x1[j], (RR)) ^ x0[j];              \
  }
#define RM(RR)                                                        \
  _Pragma("unroll") for (int j = 0; j < 2; j++) {                     \
    x0[j] += x1[j];                                                   \
    const uint64_t p = (uint64_t)x1[j] * (uint64_t)(1u << (RR));      \
    x1[j] = x0[j] ^ (uint32_t)p ^ (uint32_t)(p >> 32);                \
  }

__device__ __forceinline__ void gen2(U4 kk, uint32_t ctrA, uint32_t ctrB,
                                     float* out) {
  const uint32_t ks0 = kk.x, ks1 = kk.y, ks2 = kk.z;
  uint32_t x0[2], x1[2];
  x0[0] = ks0; x1[0] = ctrA + ks1;
  x0[1] = ks0; x1[1] = ctrB + ks1;
  // 12 of 20 rounds on the fma pipe (IMAD.WIDE), 8 on alu (SHF)
  RM(13) RS(15) RM(26) RS(6)
#pragma unroll
  for (int j = 0; j < 2; j++) { x0[j] += ks1; x1[j] += ks2 + 1u; }
  RM(17) RS(29) RM(16) RS(24)
#pragma unroll
  for (int j = 0; j < 2; j++) { x0[j] += ks2; x1[j] += ks0 + 2u; }
  RM(13) RS(15) RM(26) RS(6)
#pragma unroll
  for (int j = 0; j < 2; j++) { x0[j] += ks0; x1[j] += ks1 + 3u; }
  RM(17) RM(29) RS(16) RM(24)
#pragma unroll
  for (int j = 0; j < 2; j++) { x0[j] += ks1; x1[j] += ks2 + 4u; }
  RM(13) RM(15) RS(26) RM(6)

  float uu[2], ww[2];
#pragma unroll
  for (int j = 0; j < 2; j++) {
    const uint32_t bits = (x0[j] + ks2) ^ (x1[j] + ks0 + 5u);   // o0 ^ o1
    const float f = __uint_as_float((bits >> 9) | 0x3f800000u) - 1.0f;
    uu[j] = fmaf(f, 2.0f, -0.99999994f);
    ww[j] = -__logf(fmaf(-uu[j], uu[j], 1.0f));
  }
#pragma unroll
  for (int j = 0; j < 2; j++) {
    float w = ww[j], p;
    if (w < 5.0f) {  // XLA ErfInv32 (Giles)
      w -= 2.5f;
      p =             2.81022636e-08f;
      p = fmaf(p, w,  3.43273939e-07f);
      p = fmaf(p, w, -3.5233877e-06f);
      p = fmaf(p, w, -4.39150654e-06f);
      p = fmaf(p, w,  0.00021858087f);
      p = fmaf(p, w, -0.00125372503f);
      p = fmaf(p, w, -0.00417768164f);
      p = fmaf(p, w,  0.246640727f);
      p = fmaf(p, w,  1.50140941f);
    } else {
      w = sqrtf(w) - 3.0f;
      p =            -0.000200214257f;
      p = fmaf(p, w,  0.000100950558f);
      p = fmaf(p, w,  0.00134934322f);
      p = fmaf(p, w, -0.00367342844f);
      p = fmaf(p, w,  0.00573950773f);
      p = fmaf(p, w, -0.0076224613f);
      p = fmaf(p, w,  0.00943887047f);
      p = fmaf(p, w,  1.00167406f);
      p = fmaf(p, w,  2.83297682f);
    }
    out[j] = 1.41421356f * (p * uu[j]);
  }
}

__device__ __forceinline__ float tanh_fast(float x) {
  float y;
  asm("tanh.approx.f32 %0, %1;" : "=f"(y) : "f"(x));
  return y;
}

// =================== fused producer/consumer-in-block kernel ===================
__global__ void __launch_bounds__(TPB, 5) fused_all(
    const float* __restrict__ skes, const float* __restrict__ silT_g,
    const float* __restrict__ w_skes, const float* __restrict__ w_sil_p,
    const float* __restrict__ t_scale_p, float* __restrict__ preds)
{
  __shared__ U4    s_key[NSTEP];
  __shared__ float s_buf[2][CSTEP][EPB];

  const int tid  = threadIdx.x;
  const int lane = tid & 31;
  const int wid  = tid >> 5;            // 0..7
  const int base = blockIdx.x * EPB;
  const uint32_t ctrA = (uint32_t)(base + lane);
  const uint32_t ctrB = ctrA + 32u;

  for (int j = tid; j < NSTEP; j += TPB) s_key[j] = c_sched.key[j];

  // solver-only state (tid < EPB)
  float sil = 0.f, silT = 0.f, cond = 0.f, wsil = 0.f, tsc = 0.f;
  if (tid < EPB) {
    const int i  = base + tid;
    const int ns = i / HW;
    const int r  = i - ns * HW;
    const int n  = ns >> 3, sf = ns & 7;
    const float* bp = skes + (size_t)(n * 24 + sf) * HW + r;   // c stride = 8*HW
    cond = bp[0] * w_skes[0] + bp[8 * HW] * w_skes[1] + bp[16 * HW] * w_skes[2];
    silT = silT_g[i];
    wsil = *w_sil_p;
    tsc  = *t_scale_p;
    sil  = silT;
  }
  __syncthreads();

  // ---- prologue: chunk 0, warp w covers steps w, w+8, ... ----
  for (int s = wid; s < CSTEP; s += 8) {
    float o[2];
    gen2(s_key[s], ctrA, ctrB, o);
    s_buf[0][s][lane]      = o[0];
    s_buf[0][s][lane + 32] = o[1];
  }
  __syncthreads();

  // ---- main loop: 20 chunks ----
  for (int g = 0; g < NCHUNK; g++) {
    const int cb = g & 1, nb = cb ^ 1;

    if (g < NCHUNK - 1) {
      const int kb = (g + 1) * CSTEP;
      if (wid >= 2) {
        // producer warp w: steps [2 + (w-2)*8, +8)
        const int sbase = kb + 2 + (wid - 2) * 8;
#pragma unroll
        for (int jp = 0; jp < 8; jp++) {
          float o[2];
          gen2(s_key[sbase + jp], ctrA, ctrB, o);
          s_buf[nb][2 + (wid - 2) * 8 + jp][lane]      = o[0];
          s_buf[nb][2 + (wid - 2) * 8 + jp][lane + 32] = o[1];
        }
      } else {
        // solver warps: one step each (steps 0 and 1 of next chunk)
        float o[2];
        gen2(s_key[kb + wid], ctrA, ctrB, o);
        s_buf[nb][wid][lane]      = o[0];
        s_buf[nb][wid][lane + 32] = o[1];
      }
    }

    if (tid < EPB) {
      // consume current chunk: 50 sequential DDIM steps
      float* op = preds + (size_t)(g * CSTEP) * NELEM + base + tid;
#pragma unroll 5
      for (int u = 0; u < CSTEP; u++) {
        const F4 c = c_sched.sc[g * CSTEP + u];   // uniform -> const cache
        const float z  = fmaf(wsil, sil, fmaf(tsc, c.w, cond));
        const float s0 = tanh_fast(z);
        op[(size_t)u * NELEM] = s0;
        sil = fmaf(c.x, s0, fmaf(c.z, s_buf[cb][u][tid], c.y * silT));
      }
    }
    __syncthreads();
  }
}

// =================== launch ===================
extern "C" void kernel_launch(void* const* d_in, const int* in_sizes, int n_in,
                              void* d_out, int out_size) {
  const float* skes    = (const float*)d_in[0];  // (2,3,8,64,44)
  const float* sil_T   = (const float*)d_in[1];  // (16,1,64,44)
  const float* w_skes  = (const float*)d_in[2];  // (3,)
  const float* w_sil   = (const float*)d_in[3];  // ()
  const float* t_scale = (const float*)d_in[4];  // ()
  float* preds = (float*)d_out;                  // (1000,16,1,64,44)

  fused_all<<<NBLK, TPB>>>(skes, sil_T, w_skes, w_sil, t_scale, preds);
}

// round 9
// speedup vs baseline: 2.3986x; 1.0261x over previous
#include <cuda_runtime.h>
#include <stdint.h>

#define NSTEP  1000
#define NELEM  45056     // 16*1*64*44
#define HW     2816      // 64*44
#define EPB    64        // elements per block
#define TPB    256       // warps 0-1 solver(+4 gens), 2-7 producers (7 gens)
#define NBLK   704       // 45056 / 64
#define CSTEP  50        // steps per chunk
#define NCHUNK 20        // 1000 / 50

// =================== compile-time schedule + folded keys ===================
struct alignas(16) F4 { float x, y, z, w; };
struct alignas(16) U4 { unsigned x, y, z, w; };   // {ks0, ks1, ks2, 0}

struct SchedData {
  F4 sc[NSTEP];     // {P, Q, C1, TCO}
  U4 key[NSTEP];    // {ks0, ks1, ks2, 0}
};

constexpr double csqrt(double x) {
  double r = (x > 1.0) ? x : 1.0;
  for (int i = 0; i < 48; i++) r = 0.5 * (r + x / r);
  return r;
}
constexpr unsigned crotl(unsigned v, int r) { return (v << r) | (v >> (32 - r)); }
constexpr void ctf_round(unsigned& x0, unsigned& x1, int r) {
  x0 += x1; x1 = crotl(x1, r); x1 ^= x0;
}
constexpr void cthreefry(unsigned ks0, unsigned ks1, unsigned x0, unsigned x1,
                         unsigned& o0, unsigned& o1) {
  const unsigned ks2 = ks0 ^ ks1 ^ 0x1BD11BDAu;
  x0 += ks0; x1 += ks1;
  ctf_round(x0,x1,13); ctf_round(x0,x1,15); ctf_round(x0,x1,26); ctf_round(x0,x1,6);
  x0 += ks1; x1 += ks2 + 1u;
  ctf_round(x0,x1,17); ctf_round(x0,x1,29); ctf_round(x0,x1,16); ctf_round(x0,x1,24);
  x0 += ks2; x1 += ks0 + 2u;
  ctf_round(x0,x1,13); ctf_round(x0,x1,15); ctf_round(x0,x1,26); ctf_round(x0,x1,6);
  x0 += ks0; x1 += ks1 + 3u;
  ctf_round(x0,x1,17); ctf_round(x0,x1,29); ctf_round(x0,x1,16); ctf_round(x0,x1,24);
  x0 += ks1; x1 += ks2 + 4u;
  ctf_round(x0,x1,13); ctf_round(x0,x1,15); ctf_round(x0,x1,26); ctf_round(x0,x1,6);
  o0 = x0 + ks2;
  o1 = x1 + ks0 + 5u;
}

constexpr SchedData make_sched() {
  SchedData s{};
  double alph[NSTEP + 1] = {};
  alph[0] = 1.0;
  {
    double prod = 1.0;
    const double bstep = (0.02 - 1e-4) / 999.0;
    for (int i = 0; i < NSTEP; i++) {
      double beta = (i == 999) ? 0.02 : (1e-4 + (double)i * bstep);
      prod *= (1.0 - beta);
      alph[i + 1] = prod;
    }
  }
  for (int k = 0; k < NSTEP; k++) {
    const int idx = 999 - k;
    const float at  = (float)alph[idx + 1];
    const float atn = (float)alph[idx];            // k==999 -> 1.0
    const float a1  = 1.0f - at / atn;
    const float c1  = 0.1f * (float)csqrt((double)(a1 * (1.0f - atn) / (1.0f - at)));
    float t2 = 1.0f - atn - c1 * c1; if (t2 < 0.0f) t2 = 0.0f;
    const float c2  = (float)csqrt((double)t2);
    const double s1 = csqrt(1.0 - (double)at);
    const double Qd = (double)c2 / s1;                               // coeff of sil_T
    const double Pd = (double)(float)csqrt((double)atn)
                    - Qd * (double)(float)csqrt((double)at);         // coeff of sil_0
    s.sc[k].x = (float)Pd; s.sc[k].y = (float)Qd; s.sc[k].z = c1;
    s.sc[k].w = (float)idx / 1000.0f;
    unsigned k0 = 0, k1 = 0;
    cthreefry(0u, 42u, 0u, (unsigned)idx, k0, k1);   // fold_in(key(42), idx)
    s.key[k].x = k0; s.key[k].y = k1;
    s.key[k].z = k0 ^ k1 ^ 0x1BD11BDAu;
    s.key[k].w = 0u;
  }
  return s;
}

__constant__ SchedData c_sched = make_sched();

// =================== 2-element interleaved threefry -> 2 normals ===================
#define R2(RR)                                                 \
  _Pragma("unroll") for (int j = 0; j < 2; j++) {              \
    x0[j] += x1[j];                                            \
    x1[j] = __funnelshift_l(x1[j], x1[j], (RR)) ^ x0[j];       \
  }

__device__ __forceinline__ void gen2(U4 kk, uint32_t ctrA, uint32_t ctrB,
                                     float* out) {
  const uint32_t ks0 = kk.x, ks1 = kk.y, ks2 = kk.z;
  uint32_t x0[2], x1[2];
  x0[0] = ks0; x1[0] = ctrA + ks1;
  x0[1] = ks0; x1[1] = ctrB + ks1;
  R2(13) R2(15) R2(26) R2(6)
#pragma unroll
  for (int j = 0; j < 2; j++) { x0[j] += ks1; x1[j] += ks2 + 1u; }
  R2(17) R2(29) R2(16) R2(24)
#pragma unroll
  for (int j = 0; j < 2; j++) { x0[j] += ks2; x1[j] += ks0 + 2u; }
  R2(13) R2(15) R2(26) R2(6)
#pragma unroll
  for (int j = 0; j < 2; j++) { x0[j] += ks0; x1[j] += ks1 + 3u; }
  R2(17) R2(29) R2(16) R2(24)
#pragma unroll
  for (int j = 0; j < 2; j++) { x0[j] += ks1; x1[j] += ks2 + 4u; }
  R2(13) R2(15) R2(26) R2(6)

  float uu[2], ww[2];
#pragma unroll
  for (int j = 0; j < 2; j++) {
    const uint32_t bits = (x0[j] + ks2) ^ (x1[j] + ks0 + 5u);   // o0 ^ o1
    const float f = __uint_as_float((bits >> 9) | 0x3f800000u) - 1.0f;
    uu[j] = fmaf(f, 2.0f, -0.99999994f);
    ww[j] = -__logf(fmaf(-uu[j], uu[j], 1.0f));
  }
#pragma unroll
  for (int j = 0; j < 2; j++) {
    float w = ww[j], p;
    if (w < 5.0f) {  // XLA ErfInv32 (Giles)
      w -= 2.5f;
      p =             2.81022636e-08f;
      p = fmaf(p, w,  3.43273939e-07f);
      p = fmaf(p, w, -3.5233877e-06f);
      p = fmaf(p, w, -4.39150654e-06f);
      p = fmaf(p, w,  0.00021858087f);
      p = fmaf(p, w, -0.00125372503f);
      p = fmaf(p, w, -0.00417768164f);
      p = fmaf(p, w,  0.246640727f);
      p = fmaf(p, w,  1.50140941f);
    } else {
      w = sqrtf(w) - 3.0f;
      p =            -0.000200214257f;
      p = fmaf(p, w,  0.000100950558f);
      p = fmaf(p, w,  0.00134934322f);
      p = fmaf(p, w, -0.00367342844f);
      p = fmaf(p, w,  0.00573950773f);
      p = fmaf(p, w, -0.0076224613f);
      p = fmaf(p, w,  0.00943887047f);
      p = fmaf(p, w,  1.00167406f);
      p = fmaf(p, w,  2.83297682f);
    }
    out[j] = 1.41421356f * (p * uu[j]);
  }
}

__device__ __forceinline__ float tanh_fast(float x) {
  float y;
  asm("tanh.approx.f32 %0, %1;" : "=f"(y) : "f"(x));
  return y;
}

// =================== fused producer/consumer-in-block kernel ===================
__global__ void __launch_bounds__(TPB, 4) fused_all(
    const float* __restrict__ skes, const float* __restrict__ silT_g,
    const float* __restrict__ w_skes, const float* __restrict__ w_sil_p,
    const float* __restrict__ t_scale_p, float* __restrict__ preds)
{
  __shared__ float s_buf[2][CSTEP][EPB];

  const int tid  = threadIdx.x;
  const int lane = tid & 31;
  const int wid  = tid >> 5;            // 0..7
  const int base = blockIdx.x * EPB;
  const uint32_t ctrA = (uint32_t)(base + lane);
  const uint32_t ctrB = ctrA + 32u;

  // solver-only state (tid < EPB)
  float sil = 0.f, silT = 0.f, cond = 0.f, wsil = 0.f, tsc = 0.f;
  if (tid < EPB) {
    const int i  = base + tid;
    const int ns = i / HW;
    const int r  = i - ns * HW;
    const int n  = ns >> 3, sf = ns & 7;
    const float* bp = skes + (size_t)(n * 24 + sf) * HW + r;   // c stride = 8*HW
    cond = bp[0] * w_skes[0] + bp[8 * HW] * w_skes[1] + bp[16 * HW] * w_skes[2];
    silT = silT_g[i];
    wsil = *w_sil_p;
    tsc  = *t_scale_p;
    sil  = silT;
  }

  // ---- prologue: chunk 0 — warp w covers steps w, w+8, ... ----
  for (int s = wid; s < CSTEP; s += 8) {
    float o[2];
    gen2(c_sched.key[s], ctrA, ctrB, o);
    s_buf[0][s][lane]      = o[0];
    s_buf[0][s][lane + 32] = o[1];
  }
  __syncthreads();

  // ---- main loop: 20 chunks ----
  // quotas per chunk: solver warps 0-1 -> 4 gens each; producers 2-7 -> 7 each
  for (int g = 0; g < NCHUNK; g++) {
    const int cb = g & 1, nb = cb ^ 1;

    if (g < NCHUNK - 1) {
      const int kb = (g + 1) * CSTEP;
      if (wid >= 2) {
        const int sb = 8 + (wid - 2) * 7;       // steps [sb, sb+7)
#pragma unroll
        for (int jp = 0; jp < 7; jp++) {
          float o[2];
          gen2(c_sched.key[kb + sb + jp], ctrA, ctrB, o);
          s_buf[nb][sb + jp][lane]      = o[0];
          s_buf[nb][sb + jp][lane + 32] = o[1];
        }
      } else {
        const int sb = wid * 4;                 // steps [sb, sb+4)
#pragma unroll
        for (int jp = 0; jp < 4; jp++) {
          float o[2];
          gen2(c_sched.key[kb + sb + jp], ctrA, ctrB, o);
          s_buf[nb][sb + jp][lane]      = o[0];
          s_buf[nb][sb + jp][lane + 32] = o[1];
        }
      }
    }

    if (tid < EPB) {
      // consume current chunk: 50 sequential DDIM steps
      float* op = preds + (size_t)(g * CSTEP) * NELEM + base + tid;
#pragma unroll 5
      for (int u = 0; u < CSTEP; u++) {
        const F4 c = c_sched.sc[g * CSTEP + u];   // uniform -> const cache
        const float z  = fmaf(wsil, sil, fmaf(tsc, c.w, cond));
        const float s0 = tanh_fast(z);
        op[(size_t)u * NELEM] = s0;
        sil = fmaf(c.x, s0, fmaf(c.z, s_buf[cb][u][tid], c.y * silT));
      }
    }
    __syncthreads();
  }
}

// =================== launch ===================
extern "C" void kernel_launch(void* const* d_in, const int* in_sizes, int n_in,
                              void* d_out, int out_size) {
  const float* skes    = (const float*)d_in[0];  // (2,3,8,64,44)
  const float* sil_T   = (const float*)d_in[1];  // (16,1,64,44)
  const float* w_skes  = (const float*)d_in[2];  // (3,)
  const float* w_sil   = (const float*)d_in[3];  // ()
  const float* t_scale = (const float*)d_in[4];  // ()
  float* preds = (float*)d_out;                  // (1000,16,1,64,44)

  fused_all<<<NBLK, TPB>>>(skes, sil_T, w_skes, w_sil, t_scale, preds);
}